// round 8
// baseline (speedup 1.0000x reference)
#include <cuda_runtime.h>
#include <cuda_bf16.h>
#include <math.h>
#include <stdint.h>

// ---------------------------------------------------------------------------
// Problem constants
// ---------------------------------------------------------------------------
#define TT   2048      // seq len T
#define HIDD 2048      // hidden dim
#define NH   16        // q heads
#define NKV  8         // kv heads
#define HD   128       // head dim
#define II   8192      // mlp intermediate
#define EPSF 1e-6f
#define SCALEF 0.08838834764831845f   // 1/sqrt(128)

// ---------------------------------------------------------------------------
// Scratch (device globals; no allocation allowed)
// ---------------------------------------------------------------------------
__device__ float g_x      [TT * HIDD];        // raw input, transposed to [T][HID]
__device__ float g_q      [TT * NH  * HD];
__device__ float g_k      [TT * NKV * HD];
__device__ float g_v      [TT * NKV * HD];
__device__ float g_hidden [TT * HIDD];        // residual after attention
__device__ float g_gu     [TT * 2 * II];      // gate_up output (fp32)
__device__ float g_final  [TT * HIDD];        // final hidden (pre-transpose)
__device__ float g_rms    [TT];               // input-ln inv-rms per t

// bf16 hi/lo split operands for tensor-core GEMMs
__device__ __nv_bfloat16 g_h_hi  [TT * HIDD],      g_h_lo  [TT * HIDD];
__device__ __nv_bfloat16 g_h2_hi [TT * HIDD],      g_h2_lo [TT * HIDD];
__device__ __nv_bfloat16 g_ao_hi [TT * NH * HD],   g_ao_lo [TT * NH * HD];
__device__ __nv_bfloat16 g_act_hi[TT * II],        g_act_lo[TT * II];
__device__ __nv_bfloat16 g_wqkv_hi[(NH + 2 * NKV) * HD * HIDD], g_wqkv_lo[(NH + 2 * NKV) * HD * HIDD];
__device__ __nv_bfloat16 g_wo_hi [HIDD * NH * HD], g_wo_lo [HIDD * NH * HD];
__device__ __nv_bfloat16 g_wgu_hi[2 * II * HIDD],  g_wgu_lo[2 * II * HIDD];
__device__ __nv_bfloat16 g_wd_hi [HIDD * II],      g_wd_lo [HIDD * II];

// ---------------------------------------------------------------------------
// base-ISA PTX helpers (compute_103-safe: cp.async / ldmatrix / mma.sync)
// ---------------------------------------------------------------------------
__device__ __forceinline__ uint32_t smem_u32(const void* p) {
    uint32_t a;
    asm("{ .reg .u64 t; cvta.to.shared.u64 t, %1; cvt.u32.u64 %0, t; }"
        : "=r"(a) : "l"(p));
    return a;
}
#define CPA(dst, src) \
    asm volatile("cp.async.cg.shared.global [%0], [%1], 16;" :: "r"(dst), "l"(src))
#define CPA_COMMIT() asm volatile("cp.async.commit_group;" ::: "memory")
#define CPA_WAIT(n)  asm volatile("cp.async.wait_group %0;" :: "n"(n) : "memory")

#define LDSM4(r0, r1, r2, r3, a) \
    asm volatile("ldmatrix.sync.aligned.m8n8.x4.shared.b16 {%0,%1,%2,%3}, [%4];" \
                 : "=r"(r0), "=r"(r1), "=r"(r2), "=r"(r3) : "r"(a))

#define MMA16816(c, a0, a1, a2, a3, b0, b1) \
    asm volatile("mma.sync.aligned.m16n8k16.row.col.f32.bf16.bf16.f32 " \
                 "{%0,%1,%2,%3}, {%4,%5,%6,%7}, {%8,%9}, {%0,%1,%2,%3};" \
                 : "+f"((c)[0]), "+f"((c)[1]), "+f"((c)[2]), "+f"((c)[3]) \
                 : "r"(a0), "r"(a1), "r"(a2), "r"(a3), "r"(b0), "r"(b1))

// ---------------------------------------------------------------------------
// 1) input RMS pass 1: sum of squares per t (x[t,c] = hc[c*T + t])
// ---------------------------------------------------------------------------
__global__ void k_rms_in_pass1(const float* __restrict__ hc) {
    int tx = threadIdx.x, ty = threadIdx.y;         // 32 x 8
    int t = blockIdx.x * 32 + tx;
    float ss = 0.f;
    for (int c = ty; c < HIDD; c += 8) {
        float v = hc[c * TT + t];
        ss += v * v;
    }
    __shared__ float red[8][32];
    red[ty][tx] = ss;
    __syncthreads();
    if (ty == 0) {
        float s = 0.f;
        #pragma unroll
        for (int i = 0; i < 8; i++) s += red[i][tx];
        g_rms[t] = rsqrtf(s * (1.0f / HIDD) + EPSF);
    }
}

// ---------------------------------------------------------------------------
// 2) transpose + scale: g_x raw, g_h_hi/lo = bf16 split of normed value
// ---------------------------------------------------------------------------
__global__ void k_norm_transpose(const float* __restrict__ hc,
                                 const float* __restrict__ w) {
    __shared__ float tile[32][33];
    int t0 = blockIdx.x * 32, c0 = blockIdx.y * 32;
    int tx = threadIdx.x, ty = threadIdx.y;          // 32 x 8
    for (int i = ty; i < 32; i += 8)
        tile[i][tx] = hc[(c0 + i) * TT + t0 + tx];
    __syncthreads();
    for (int i = ty; i < 32; i += 8) {
        int t = t0 + i, c = c0 + tx;
        float val = tile[tx][i];
        g_x[(size_t)t * HIDD + c] = val;
        float nv = val * g_rms[t] * w[c];
        __nv_bfloat16 hv = __float2bfloat16(nv);
        g_h_hi[(size_t)t * HIDD + c] = hv;
        g_h_lo[(size_t)t * HIDD + c] = __float2bfloat16(nv - __bfloat162float(hv));
    }
}

// ---------------------------------------------------------------------------
// 3) weight fp32 -> bf16 hi/lo conversion (8 elems/thread, vector I/O)
// ---------------------------------------------------------------------------
__global__ void k_wconv(const float* __restrict__ src,
                        __nv_bfloat16* __restrict__ hi,
                        __nv_bfloat16* __restrict__ lo, int n) {
    int i8 = (blockIdx.x * 256 + threadIdx.x) * 8;
    if (i8 >= n) return;
    float4 v0 = *(const float4*)(src + i8);
    float4 v1 = *(const float4*)(src + i8 + 4);
    float vv[8] = {v0.x, v0.y, v0.z, v0.w, v1.x, v1.y, v1.z, v1.w};
    __nv_bfloat16 hb[8], lb[8];
    #pragma unroll
    for (int j = 0; j < 8; j++) {
        hb[j] = __float2bfloat16(vv[j]);
        lb[j] = __float2bfloat16(vv[j] - __bfloat162float(hb[j]));
    }
    *(uint4*)(hi + i8) = *(uint4*)hb;
    *(uint4*)(lo + i8) = *(uint4*)lb;
}

// ---------------------------------------------------------------------------
// 4) mma.sync bf16 GEMM: C[M,N] = (Ah+Al)[M,K] @ (Bh+Bl)[N,K]^T (3-term)
//    256x128x32 CTA tile, 256 threads = 8 warps (4m x 2n), warp 64x64.
//    cp.async 3-stage pipeline. smem rows padded to 40 bf16 (80 B).
//    MODE 0: store  MODE 1: C = acc + aux  MODE 2: QKV routing
// ---------------------------------------------------------------------------
#define BMM 256
#define BNN 128
#define OFF_AH 0
#define OFF_AL (BMM * 80)              // 20480
#define OFF_BH (2 * BMM * 80)          // 40960
#define OFF_BL (2 * BMM * 80 + BNN * 80)   // 51200
#define STG_BYTES (2 * BMM * 80 + 2 * BNN * 80)   // 61440
#define MM_SMEM (3 * STG_BYTES)        // 184320 (>= 256*132*4 epilogue)

__device__ __forceinline__ void bmma_load_stage(
    uint32_t sbase, const __nv_bfloat16* Ah, const __nv_bfloat16* Al,
    const __nv_bfloat16* Bh, const __nv_bfloat16* Bl,
    int m0, int n0, int K, int kc, int tid)
{
    size_t kbase = (size_t)kc * 32;
    #pragma unroll
    for (int i = 0; i < 4; i++) {               // A: 256 rows x 4 segs
        int f = tid + i * 256;
        int r = f >> 2, seg = f & 3;
        uint32_t dst = sbase + r * 80 + seg * 16;
        size_t so = (size_t)(m0 + r) * K + kbase + seg * 8;
        CPA(dst + OFF_AH, Ah + so);
        CPA(dst + OFF_AL, Al + so);
    }
    #pragma unroll
    for (int i = 0; i < 2; i++) {               // B: 128 rows x 4 segs
        int f = tid + i * 256;
        int r = f >> 2, seg = f & 3;
        uint32_t dst = sbase + r * 80 + seg * 16;
        size_t so = (size_t)(n0 + r) * K + kbase + seg * 8;
        CPA(dst + OFF_BH, Bh + so);
        CPA(dst + OFF_BL, Bl + so);
    }
}

template <int MODE>
__global__ __launch_bounds__(256, 1)
void k_bmma(const __nv_bfloat16* __restrict__ Ah, const __nv_bfloat16* __restrict__ Al,
            const __nv_bfloat16* __restrict__ Bh, const __nv_bfloat16* __restrict__ Bl,
            float* __restrict__ Cbase, const float* __restrict__ aux,
            int K, int N) {
    extern __shared__ char smem[];
    uint32_t sb = smem_u32(smem);
    int tid = threadIdx.x;
    int m0 = blockIdx.y * BMM, n0 = blockIdx.x * BNN;
    int warp = tid >> 5, lane = tid & 31;
    int wm = warp >> 1, wn = warp & 1;           // warp tile: 64m x 64n

    float acc[4][8][4];
    #pragma unroll
    for (int i = 0; i < 4; i++)
        #pragma unroll
        for (int j = 0; j < 8; j++)
            #pragma unroll
            for (int v = 0; v < 4; v++) acc[i][j][v] = 0.f;

    // per-thread ldmatrix offsets (within a tile, bytes; 80 B pitch)
    uint32_t a_off = (lane & 15) * 80 + (lane >> 4) * 16;
    uint32_t b_off = ((lane >> 4) * 8 + (lane & 7)) * 80 + ((lane >> 3) & 1) * 16;

    const int KC = K / 32;

    bmma_load_stage(sb, Ah, Al, Bh, Bl, m0, n0, K, 0, tid);
    CPA_COMMIT();
    bmma_load_stage(sb + STG_BYTES, Ah, Al, Bh, Bl, m0, n0, K, 1, tid);
    CPA_COMMIT();

    for (int kc = 0; kc < KC; kc++) {
        if (kc + 2 < KC) { CPA_WAIT(1); } else { CPA_WAIT(0); }
        __syncthreads();
        if (kc + 2 < KC) {
            bmma_load_stage(sb + ((kc + 2) % 3) * STG_BYTES, Ah, Al, Bh, Bl,
                            m0, n0, K, kc + 2, tid);
            CPA_COMMIT();
        }

        uint32_t stg = sb + (kc % 3) * STG_BYTES;
        uint32_t aBase = stg + wm * (64 * 80) + a_off;
        uint32_t bBase = stg + wn * (64 * 80) + b_off;

        #pragma unroll
        for (int ks = 0; ks < 2; ks++) {
            uint32_t ko = ks * 32;               // 16 bf16 = 32 bytes
            uint32_t ah[4][4], al[4][4], bh[8][2];
            #pragma unroll
            for (int im = 0; im < 4; im++)
                LDSM4(ah[im][0], ah[im][1], ah[im][2], ah[im][3],
                      aBase + OFF_AH + im * (16 * 80) + ko);
            #pragma unroll
            for (int g = 0; g < 4; g++) {
                uint32_t r0, r1, r2, r3;
                LDSM4(r0, r1, r2, r3, bBase + OFF_BH + g * (16 * 80) + ko);
                bh[g * 2 + 0][0] = r0; bh[g * 2 + 0][1] = r1;
                bh[g * 2 + 1][0] = r2; bh[g * 2 + 1][1] = r3;
            }
            #pragma unroll
            for (int im = 0; im < 4; im++)
                #pragma unroll
                for (int in = 0; in < 8; in++)
                    MMA16816(acc[im][in], ah[im][0], ah[im][1], ah[im][2], ah[im][3],
                             bh[in][0], bh[in][1]);
            // A_lo x B_hi (bh still live)
            #pragma unroll
            for (int im = 0; im < 4; im++)
                LDSM4(al[im][0], al[im][1], al[im][2], al[im][3],
                      aBase + OFF_AL + im * (16 * 80) + ko);
            #pragma unroll
            for (int im = 0; im < 4; im++)
                #pragma unroll
                for (int in = 0; in < 8; in++)
                    MMA16816(acc[im][in], al[im][0], al[im][1], al[im][2], al[im][3],
                             bh[in][0], bh[in][1]);
            // A_hi x B_lo (reuse bh regs for bl)
            #pragma unroll
            for (int g = 0; g < 4; g++) {
                uint32_t r0, r1, r2, r3;
                LDSM4(r0, r1, r2, r3, bBase + OFF_BL + g * (16 * 80) + ko);
                bh[g * 2 + 0][0] = r0; bh[g * 2 + 0][1] = r1;
                bh[g * 2 + 1][0] = r2; bh[g * 2 + 1][1] = r3;
            }
            #pragma unroll
            for (int im = 0; im < 4; im++)
                #pragma unroll
                for (int in = 0; in < 8; in++)
                    MMA16816(acc[im][in], ah[im][0], ah[im][1], ah[im][2], ah[im][3],
                             bh[in][0], bh[in][1]);
        }
        __syncthreads();
    }

    // ---- epilogue: regs -> smem (pitch 132) -> coalesced global ----
    CPA_WAIT(0);
    __syncthreads();
    float* stile = (float*)smem;
    int qrow = lane >> 2, qcol = (lane & 3) * 2;
    #pragma unroll
    for (int im = 0; im < 4; im++) {
        int r0 = wm * 64 + im * 16 + qrow;
        #pragma unroll
        for (int in = 0; in < 8; in++) {
            int c = wn * 64 + in * 8 + qcol;
            stile[(size_t)r0 * 132 + c]           = acc[im][in][0];
            stile[(size_t)r0 * 132 + c + 1]       = acc[im][in][1];
            stile[(size_t)(r0 + 8) * 132 + c]     = acc[im][in][2];
            stile[(size_t)(r0 + 8) * 132 + c + 1] = acc[im][in][3];
        }
    }
    __syncthreads();

    float* Cp; int ldc; int ncol;
    if (MODE == 2) {
        if (n0 < NH * HD)             { Cp = g_q; ldc = NH * HD;  ncol = n0; }
        else if (n0 < (NH + NKV) * HD){ Cp = g_k; ldc = NKV * HD; ncol = n0 - NH * HD; }
        else                          { Cp = g_v; ldc = NKV * HD; ncol = n0 - (NH + NKV) * HD; }
    } else { Cp = Cbase; ldc = N; ncol = n0; }

    #pragma unroll
    for (int st = 0; st < 32; st++) {
        int idx = st * 256 + tid;
        int m = idx >> 5;
        int c4 = (idx & 31) * 4;
        const float* srow = &stile[(size_t)m * 132 + c4];
        float4 v;
        v.x = srow[0]; v.y = srow[1]; v.z = srow[2]; v.w = srow[3];
        size_t go = (size_t)(m0 + m) * ldc + ncol + c4;
        if (MODE == 1) {
            float4 a4 = *(const float4*)(aux + go);
            v.x += a4.x; v.y += a4.y; v.z += a4.z; v.w += a4.w;
        }
        *(float4*)(Cp + go) = v;
    }
}

// ---------------------------------------------------------------------------
// 5) per-(t,head) RMSNorm + RoPE (in-place on g_q / g_k)
// ---------------------------------------------------------------------------
__global__ void k_qknorm_rope(const float* __restrict__ cosb,
                              const float* __restrict__ sinb,
                              const float* __restrict__ qw,
                              const float* __restrict__ kw) {
    int t = blockIdx.x;
    int head = blockIdx.y;
    float* buf; const float* w; int off;
    if (head < NH) { buf = g_q; off = (t * NH + head) * HD; w = qw; }
    else           { buf = g_k; off = (t * NKV + (head - NH)) * HD; w = kw; }
    int d = threadIdx.x;
    float v = buf[off + d];
    float ss = v * v;
    #pragma unroll
    for (int o = 16; o; o >>= 1) ss += __shfl_xor_sync(~0u, ss, o);
    __shared__ float ws[4];
    if ((d & 31) == 0) ws[d >> 5] = ss;
    __syncthreads();
    float tot = ws[0] + ws[1] + ws[2] + ws[3];
    float r = rsqrtf(tot * (1.0f / HD) + EPSF);
    __shared__ float sh[HD];
    sh[d] = v * r * w[d];
    __syncthreads();
    float rot = (d < 64) ? -sh[d + 64] : sh[d - 64];
    buf[off + d] = sh[d] * cosb[t * HD + d] + rot * sinb[t * HD + d];
}

// ---------------------------------------------------------------------------
// 6) fp32 flash attention, causal, 64x64 tiles, D=128 -> bf16 hi/lo out
//    softmax stats: 4 threads per row (16 cols each), shfl reduction
// ---------------------------------------------------------------------------
#define ATT_SMEM_FLOATS (64*128 + 128*64 + 64*128 + 64*65 + 3*64)
__global__ __launch_bounds__(256)
void k_attn() {
    extern __shared__ float asm_[];
    float* Qs   = asm_;
    float* Kst  = Qs  + 64 * 128;
    float* Vs   = Kst + 128 * 64;
    float* Ps   = Vs  + 64 * 128;
    float* mrow = Ps  + 64 * 65;
    float* lrow = mrow + 64;
    float* arow = lrow + 64;

    int qt = (int)gridDim.x - 1 - (int)blockIdx.x;
    int h  = blockIdx.y;
    int kvh = h >> 1;
    int tid = threadIdx.x;
    int ty = tid >> 4, tx = tid & 15;

    for (int f = tid; f < 64 * 32; f += 256) {
        int r = f >> 5, d4 = (f & 31) * 4;
        *(float4*)&Qs[r * 128 + d4] =
            *(const float4*)&g_q[(size_t)(qt * 64 + r) * (NH * HD) + h * HD + d4];
    }
    if (tid < 64) { mrow[tid] = -1e30f; lrow[tid] = 0.f; }

    float O[4][8];
    #pragma unroll
    for (int i = 0; i < 4; i++)
        #pragma unroll
        for (int j = 0; j < 8; j++) O[i][j] = 0.f;

    for (int kt = 0; kt <= qt; kt++) {
        for (int f = tid; f < 64 * 32; f += 256) {
            int s = f & 63, d4 = (f >> 6) * 4;
            float4 kv4 = *(const float4*)&g_k[(size_t)(kt * 64 + s) * (NKV * HD) + kvh * HD + d4];
            Kst[(d4 + 0) * 64 + s] = kv4.x;
            Kst[(d4 + 1) * 64 + s] = kv4.y;
            Kst[(d4 + 2) * 64 + s] = kv4.z;
            Kst[(d4 + 3) * 64 + s] = kv4.w;
        }
        for (int f = tid; f < 64 * 32; f += 256) {
            int s = f >> 5, d4 = (f & 31) * 4;
            *(float4*)&Vs[s * 128 + d4] =
                *(const float4*)&g_v[(size_t)(kt * 64 + s) * (NKV * HD) + kvh * HD + d4];
        }
        __syncthreads();

        float sacc[4][4];
        #pragma unroll
        for (int i = 0; i < 4; i++)
            #pragma unroll
            for (int j = 0; j < 4; j++) sacc[i][j] = 0.f;

        #pragma unroll 8
        for (int k4 = 0; k4 < 32; k4++) {
            float a[4][4], b[4][4];
            #pragma unroll
            for (int i = 0; i < 4; i++)
                *(float4*)a[i] = *(const float4*)&Qs[(ty * 4 + i) * 128 + k4 * 4];
            #pragma unroll
            for (int kk = 0; kk < 4; kk++)
                *(float4*)b[kk] = *(const float4*)&Kst[(k4 * 4 + kk) * 64 + tx * 4];
            #pragma unroll
            for (int kk = 0; kk < 4; kk++)
                #pragma unroll
                for (int i = 0; i < 4; i++)
                    #pragma unroll
                    for (int j = 0; j < 4; j++)
                        sacc[i][j] += a[i][kk] * b[kk][j];
        }

        bool diag = (kt == qt);
        #pragma unroll
        for (int i = 0; i < 4; i++)
            #pragma unroll
            for (int j = 0; j < 4; j++) {
                float sv = sacc[i][j] * SCALEF;
                if (diag && (tx * 4 + j) > (ty * 4 + i)) sv = -1e30f;
                Ps[(ty * 4 + i) * 65 + tx * 4 + j] = sv;
            }
        __syncthreads();

        // row stats: 4 threads per row, 16 cols each, shfl reduce over the quad
        {
            int r = tid >> 2, qd = tid & 3;
            float* prow = &Ps[r * 65 + qd * 16];
            float mx = prow[0];
            #pragma unroll
            for (int s2 = 1; s2 < 16; s2++) mx = fmaxf(mx, prow[s2]);
            mx = fmaxf(mx, __shfl_xor_sync(~0u, mx, 1));
            mx = fmaxf(mx, __shfl_xor_sync(~0u, mx, 2));
            float mold = mrow[r];
            mx = fmaxf(mx, mold);
            float alpha = expf(mold - mx);
            float lp = 0.f;
            #pragma unroll
            for (int s2 = 0; s2 < 16; s2++) {
                float p = expf(prow[s2] - mx);
                prow[s2] = p;
                lp += p;
            }
            lp += __shfl_xor_sync(~0u, lp, 1);
            lp += __shfl_xor_sync(~0u, lp, 2);
            if (qd == 0) {
                mrow[r] = mx;
                lrow[r] = lrow[r] * alpha + lp;
                arow[r] = alpha;
            }
        }
        __syncthreads();

        #pragma unroll
        for (int i = 0; i < 4; i++) {
            float al = arow[ty * 4 + i];
            #pragma unroll
            for (int j = 0; j < 8; j++) O[i][j] *= al;
        }
        #pragma unroll 4
        for (int s2 = 0; s2 < 64; s2++) {
            float p[4];
            #pragma unroll
            for (int i = 0; i < 4; i++) p[i] = Ps[(ty * 4 + i) * 65 + s2];
            float4 v0 = *(const float4*)&Vs[s2 * 128 + tx * 8];
            float4 v1 = *(const float4*)&Vs[s2 * 128 + tx * 8 + 4];
            #pragma unroll
            for (int i = 0; i < 4; i++) {
                O[i][0] += p[i] * v0.x; O[i][1] += p[i] * v0.y;
                O[i][2] += p[i] * v0.z; O[i][3] += p[i] * v0.w;
                O[i][4] += p[i] * v1.x; O[i][5] += p[i] * v1.y;
                O[i][6] += p[i] * v1.z; O[i][7] += p[i] * v1.w;
            }
        }
        __syncthreads();
    }

    #pragma unroll
    for (int i = 0; i < 4; i++) {
        int r = ty * 4 + i;
        int t = qt * 64 + r;
        float inv = 1.0f / lrow[r];
        #pragma unroll
        for (int j = 0; j < 8; j++) {
            float v = O[i][j] * inv;
            size_t o = (size_t)t * (NH * HD) + h * HD + tx * 8 + j;
            __nv_bfloat16 hv = __float2bfloat16(v);
            g_ao_hi[o] = hv;
            g_ao_lo[o] = __float2bfloat16(v - __bfloat162float(hv));
        }
    }
}

// ---------------------------------------------------------------------------
// 7) post-attention RMSNorm -> h2 bf16 hi/lo
// ---------------------------------------------------------------------------
__global__ void k_rms_post(const float* __restrict__ w) {
    int t = blockIdx.x;
    int tid = threadIdx.x;                   // 256
    const float* row = g_hidden + (size_t)t * HIDD;
    float ss = 0.f;
    for (int c = tid; c < HIDD; c += 256) { float v = row[c]; ss += v * v; }
    #pragma unroll
    for (int o = 16; o; o >>= 1) ss += __shfl_xor_sync(~0u, ss, o);
    __shared__ float wsum[8];
    if ((tid & 31) == 0) wsum[tid >> 5] = ss;
    __syncthreads();
    if (tid < 32) {
        float s = (tid < 8) ? wsum[tid] : 0.f;
        #pragma unroll
        for (int o = 4; o; o >>= 1) s += __shfl_xor_sync(~0u, s, o);
        if (tid == 0) wsum[0] = rsqrtf(s * (1.0f / HIDD) + EPSF);
    }
    __syncthreads();
    float r = wsum[0];
    for (int c = tid; c < HIDD; c += 256) {
        float nv = row[c] * r * w[c];
        __nv_bfloat16 hv = __float2bfloat16(nv);
        g_h2_hi[(size_t)t * HIDD + c] = hv;
        g_h2_lo[(size_t)t * HIDD + c] = __float2bfloat16(nv - __bfloat162float(hv));
    }
}

// ---------------------------------------------------------------------------
// 8) SwiGLU -> act bf16 hi/lo (4 elems/thread, vector I/O)
// ---------------------------------------------------------------------------
__global__ void k_swiglu() {
    int t = blockIdx.y;
    int i = (blockIdx.x * 256 + threadIdx.x) * 4;
    float4 g4 = *(const float4*)&g_gu[(size_t)t * (2 * II) + i];
    float4 u4 = *(const float4*)&g_gu[(size_t)t * (2 * II) + II + i];
    float gg[4] = {g4.x, g4.y, g4.z, g4.w};
    float uu[4] = {u4.x, u4.y, u4.z, u4.w};
    __nv_bfloat16 hb[4], lb[4];
    #pragma unroll
    for (int j = 0; j < 4; j++) {
        float a = (gg[j] / (1.0f + expf(-gg[j]))) * uu[j];
        hb[j] = __float2bfloat16(a);
        lb[j] = __float2bfloat16(a - __bfloat162float(hb[j]));
    }
    *(uint2*)&g_act_hi[(size_t)t * II + i] = *(uint2*)hb;
    *(uint2*)&g_act_lo[(size_t)t * II + i] = *(uint2*)lb;
}

// ---------------------------------------------------------------------------
// 9) final transpose: out[c*T + t] = g_final[t*HID + c]
// ---------------------------------------------------------------------------
__global__ void k_transpose_out(float* __restrict__ out) {
    __shared__ float tile[32][33];
    int t0 = blockIdx.x * 32, c0 = blockIdx.y * 32;
    int tx = threadIdx.x, ty = threadIdx.y;     // 32 x 8
    for (int i = ty; i < 32; i += 8)
        tile[i][tx] = g_final[(size_t)(t0 + i) * HIDD + c0 + tx];
    __syncthreads();
    for (int i = ty; i < 32; i += 8)
        out[(size_t)(c0 + i) * TT + t0 + tx] = tile[tx][i];
}

// ---------------------------------------------------------------------------
// launch
// ---------------------------------------------------------------------------
extern "C" void kernel_launch(void* const* d_in, const int* in_sizes, int n_in,
                              void* d_out, int out_size) {
    const float* hc   = (const float*)d_in[0];
    const float* cosb = (const float*)d_in[1];
    const float* sinb = (const float*)d_in[2];
    // d_in[3] causal_mask, d_in[4] kv_cache, d_in[15] current_pos: unused
    const float* wq  = (const float*)d_in[5];
    const float* wk  = (const float*)d_in[6];
    const float* wv  = (const float*)d_in[7];
    const float* wo  = (const float*)d_in[8];
    const float* wgu = (const float*)d_in[9];
    const float* wd  = (const float*)d_in[10];
    const float* ilw = (const float*)d_in[11];
    const float* plw = (const float*)d_in[12];
    const float* qnw = (const float*)d_in[13];
    const float* knw = (const float*)d_in[14];
    float* out = (float*)d_out;

    float *p_x, *p_hid, *p_gu, *p_fin;
    cudaGetSymbolAddress((void**)&p_x,   g_x);
    cudaGetSymbolAddress((void**)&p_hid, g_hidden);
    cudaGetSymbolAddress((void**)&p_gu,  g_gu);
    cudaGetSymbolAddress((void**)&p_fin, g_final);

    __nv_bfloat16 *b_h_hi, *b_h_lo, *b_h2_hi, *b_h2_lo, *b_ao_hi, *b_ao_lo,
                  *b_act_hi, *b_act_lo, *b_wqkv_hi, *b_wqkv_lo, *b_wo_hi, *b_wo_lo,
                  *b_wgu_hi, *b_wgu_lo, *b_wd_hi, *b_wd_lo;
    cudaGetSymbolAddress((void**)&b_h_hi,   g_h_hi);
    cudaGetSymbolAddress((void**)&b_h_lo,   g_h_lo);
    cudaGetSymbolAddress((void**)&b_h2_hi,  g_h2_hi);
    cudaGetSymbolAddress((void**)&b_h2_lo,  g_h2_lo);
    cudaGetSymbolAddress((void**)&b_ao_hi,  g_ao_hi);
    cudaGetSymbolAddress((void**)&b_ao_lo,  g_ao_lo);
    cudaGetSymbolAddress((void**)&b_act_hi, g_act_hi);
    cudaGetSymbolAddress((void**)&b_act_lo, g_act_lo);
    cudaGetSymbolAddress((void**)&b_wqkv_hi, g_wqkv_hi);
    cudaGetSymbolAddress((void**)&b_wqkv_lo, g_wqkv_lo);
    cudaGetSymbolAddress((void**)&b_wo_hi,  g_wo_hi);
    cudaGetSymbolAddress((void**)&b_wo_lo,  g_wo_lo);
    cudaGetSymbolAddress((void**)&b_wgu_hi, g_wgu_hi);
    cudaGetSymbolAddress((void**)&b_wgu_lo, g_wgu_lo);
    cudaGetSymbolAddress((void**)&b_wd_hi,  g_wd_hi);
    cudaGetSymbolAddress((void**)&b_wd_lo,  g_wd_lo);

    const int ATT_SMEM = ATT_SMEM_FLOATS * 4;
    cudaFuncSetAttribute(k_attn, cudaFuncAttributeMaxDynamicSharedMemorySize, ATT_SMEM);
    cudaFuncSetAttribute(k_bmma<0>, cudaFuncAttributeMaxDynamicSharedMemorySize, MM_SMEM);
    cudaFuncSetAttribute(k_bmma<1>, cudaFuncAttributeMaxDynamicSharedMemorySize, MM_SMEM);
    cudaFuncSetAttribute(k_bmma<2>, cudaFuncAttributeMaxDynamicSharedMemorySize, MM_SMEM);

    // weight conversions (independent of activations)
    k_wconv<<<(NH * HD * HIDD) / 2048, 256>>>(wq, b_wqkv_hi, b_wqkv_lo, NH * HD * HIDD);
    k_wconv<<<(NKV * HD * HIDD) / 2048, 256>>>(wk, b_wqkv_hi + (size_t)NH * HD * HIDD,
                                               b_wqkv_lo + (size_t)NH * HD * HIDD, NKV * HD * HIDD);
    k_wconv<<<(NKV * HD * HIDD) / 2048, 256>>>(wv, b_wqkv_hi + (size_t)(NH + NKV) * HD * HIDD,
                                               b_wqkv_lo + (size_t)(NH + NKV) * HD * HIDD, NKV * HD * HIDD);
    k_wconv<<<(HIDD * NH * HD) / 2048, 256>>>(wo, b_wo_hi, b_wo_lo, HIDD * NH * HD);
    k_wconv<<<(2 * II * HIDD) / 2048, 256>>>(wgu, b_wgu_hi, b_wgu_lo, 2 * II * HIDD);
    k_wconv<<<(HIDD * II) / 2048, 256>>>(wd, b_wd_hi, b_wd_lo, HIDD * II);

    // 1-2) input RMSNorm + transpose (also emits raw x)
    k_rms_in_pass1<<<TT / 32, dim3(32, 8)>>>(hc);
    k_norm_transpose<<<dim3(TT / 32, HIDD / 32), dim3(32, 8)>>>(hc, ilw);

    // 3) fused QKV projection (tensor cores, routed epilogue)
    k_bmma<2><<<dim3((NH + 2 * NKV) * HD / BNN, TT / BMM), 256, MM_SMEM>>>(
        b_h_hi, b_h_lo, b_wqkv_hi, b_wqkv_lo, nullptr, nullptr, HIDD, (NH + 2 * NKV) * HD);

    // 4) q/k RMSNorm + RoPE
    k_qknorm_rope<<<dim3(TT, NH + NKV), HD>>>(cosb, sinb, qnw, knw);

    // 5) causal flash attention (fp32, bf16 hi/lo out)
    k_attn<<<dim3(TT / 64, NH), 256, ATT_SMEM>>>();

    // 6) Wo projection + residual(x)
    k_bmma<1><<<dim3(HIDD / BNN, TT / BMM), 256, MM_SMEM>>>(
        b_ao_hi, b_ao_lo, b_wo_hi, b_wo_lo, p_hid, p_x, NH * HD, HIDD);

    // 7) post-LN
    k_rms_post<<<TT, 256>>>(plw);

    // 8) gate_up GEMM
    k_bmma<0><<<dim3((2 * II) / BNN, TT / BMM), 256, MM_SMEM>>>(
        b_h2_hi, b_h2_lo, b_wgu_hi, b_wgu_lo, p_gu, nullptr, HIDD, 2 * II);

    // 9) SwiGLU
    k_swiglu<<<dim3(II / 1024, TT), 256>>>();

    // 10) down GEMM + residual
    k_bmma<1><<<dim3(HIDD / BNN, TT / BMM), 256, MM_SMEM>>>(
        b_act_hi, b_act_lo, b_wd_hi, b_wd_lo, p_fin, p_hid, II, HIDD);

    // 11) output transpose
    k_transpose_out<<<dim3(TT / 32, HIDD / 32), dim3(32, 8)>>>(out);
}

// round 11
// speedup vs baseline: 1.5563x; 1.5563x over previous
#include <cuda_runtime.h>
#include <cuda_bf16.h>
#include <math.h>
#include <stdint.h>

// ---------------------------------------------------------------------------
// Problem constants
// ---------------------------------------------------------------------------
#define TT   2048      // seq len T
#define HIDD 2048      // hidden dim
#define NH   16        // q heads
#define NKV  8         // kv heads
#define HD   128       // head dim
#define II   8192      // mlp intermediate
#define EPSF 1e-6f
#define SCALEF 0.08838834764831845f   // 1/sqrt(128)

// ---------------------------------------------------------------------------
// Scratch (device globals; no allocation allowed)
// ---------------------------------------------------------------------------
__device__ float g_x      [TT * HIDD];        // raw input, transposed to [T][HID]
__device__ float g_q      [TT * NH  * HD];
__device__ float g_k      [TT * NKV * HD];
__device__ float g_v      [TT * NKV * HD];
__device__ float g_hidden [TT * HIDD];        // residual after attention
__device__ float g_gu     [TT * 2 * II];      // gate_up output (fp32)
__device__ float g_final  [TT * HIDD];        // final hidden (pre-transpose)
__device__ float g_rms    [TT];               // input-ln inv-rms per t

// bf16 hi/lo split operands for tensor-core GEMMs
__device__ __nv_bfloat16 g_h_hi  [TT * HIDD],      g_h_lo  [TT * HIDD];
__device__ __nv_bfloat16 g_h2_hi [TT * HIDD],      g_h2_lo [TT * HIDD];
__device__ __nv_bfloat16 g_ao_hi [TT * NH * HD],   g_ao_lo [TT * NH * HD];
__device__ __nv_bfloat16 g_act_hi[TT * II],        g_act_lo[TT * II];
__device__ __nv_bfloat16 g_wqkv_hi[(NH + 2 * NKV) * HD * HIDD], g_wqkv_lo[(NH + 2 * NKV) * HD * HIDD];
__device__ __nv_bfloat16 g_wo_hi [HIDD * NH * HD], g_wo_lo [HIDD * NH * HD];
__device__ __nv_bfloat16 g_wgu_hi[2 * II * HIDD],  g_wgu_lo[2 * II * HIDD];
__device__ __nv_bfloat16 g_wd_hi [HIDD * II],      g_wd_lo [HIDD * II];

// ---------------------------------------------------------------------------
// base-ISA PTX helpers (compute_103-safe: cp.async / ldmatrix / mma.sync)
// ---------------------------------------------------------------------------
__device__ __forceinline__ uint32_t smem_u32(const void* p) {
    uint32_t a;
    asm("{ .reg .u64 t; cvta.to.shared.u64 t, %1; cvt.u32.u64 %0, t; }"
        : "=r"(a) : "l"(p));
    return a;
}
#define CPA(dst, src) \
    asm volatile("cp.async.cg.shared.global [%0], [%1], 16;" :: "r"(dst), "l"(src))
#define CPA_COMMIT() asm volatile("cp.async.commit_group;" ::: "memory")
#define CPA_WAIT(n)  asm volatile("cp.async.wait_group %0;" :: "n"(n) : "memory")

#define LDSM4(r0, r1, r2, r3, a) \
    asm volatile("ldmatrix.sync.aligned.m8n8.x4.shared.b16 {%0,%1,%2,%3}, [%4];" \
                 : "=r"(r0), "=r"(r1), "=r"(r2), "=r"(r3) : "r"(a))

#define MMA16816(c, a0, a1, a2, a3, b0, b1) \
    asm volatile("mma.sync.aligned.m16n8k16.row.col.f32.bf16.bf16.f32 " \
                 "{%0,%1,%2,%3}, {%4,%5,%6,%7}, {%8,%9}, {%0,%1,%2,%3};" \
                 : "+f"((c)[0]), "+f"((c)[1]), "+f"((c)[2]), "+f"((c)[3]) \
                 : "r"(a0), "r"(a1), "r"(a2), "r"(a3), "r"(b0), "r"(b1))

// ---------------------------------------------------------------------------
// 1) input RMS pass 1: sum of squares per t (x[t,c] = hc[c*T + t])
// ---------------------------------------------------------------------------
__global__ void k_rms_in_pass1(const float* __restrict__ hc) {
    int tx = threadIdx.x, ty = threadIdx.y;         // 32 x 8
    int t = blockIdx.x * 32 + tx;
    float ss = 0.f;
    for (int c = ty; c < HIDD; c += 8) {
        float v = hc[c * TT + t];
        ss += v * v;
    }
    __shared__ float red[8][32];
    red[ty][tx] = ss;
    __syncthreads();
    if (ty == 0) {
        float s = 0.f;
        #pragma unroll
        for (int i = 0; i < 8; i++) s += red[i][tx];
        g_rms[t] = rsqrtf(s * (1.0f / HIDD) + EPSF);
    }
}

// ---------------------------------------------------------------------------
// 2) transpose + scale: g_x raw, g_h_hi/lo = bf16 split of normed value
// ---------------------------------------------------------------------------
__global__ void k_norm_transpose(const float* __restrict__ hc,
                                 const float* __restrict__ w) {
    __shared__ float tile[32][33];
    int t0 = blockIdx.x * 32, c0 = blockIdx.y * 32;
    int tx = threadIdx.x, ty = threadIdx.y;          // 32 x 8
    for (int i = ty; i < 32; i += 8)
        tile[i][tx] = hc[(c0 + i) * TT + t0 + tx];
    __syncthreads();
    for (int i = ty; i < 32; i += 8) {
        int t = t0 + i, c = c0 + tx;
        float val = tile[tx][i];
        g_x[(size_t)t * HIDD + c] = val;
        float nv = val * g_rms[t] * w[c];
        __nv_bfloat16 hv = __float2bfloat16(nv);
        g_h_hi[(size_t)t * HIDD + c] = hv;
        g_h_lo[(size_t)t * HIDD + c] = __float2bfloat16(nv - __bfloat162float(hv));
    }
}

// ---------------------------------------------------------------------------
// 3) weight fp32 -> bf16 hi/lo conversion (8 elems/thread, vector I/O)
// ---------------------------------------------------------------------------
__global__ void k_wconv(const float* __restrict__ src,
                        __nv_bfloat16* __restrict__ hi,
                        __nv_bfloat16* __restrict__ lo, int n) {
    int i8 = (blockIdx.x * 256 + threadIdx.x) * 8;
    if (i8 >= n) return;
    float4 v0 = *(const float4*)(src + i8);
    float4 v1 = *(const float4*)(src + i8 + 4);
    float vv[8] = {v0.x, v0.y, v0.z, v0.w, v1.x, v1.y, v1.z, v1.w};
    __nv_bfloat16 hb[8], lb[8];
    #pragma unroll
    for (int j = 0; j < 8; j++) {
        hb[j] = __float2bfloat16(vv[j]);
        lb[j] = __float2bfloat16(vv[j] - __bfloat162float(hb[j]));
    }
    *(uint4*)(hi + i8) = *(uint4*)hb;
    *(uint4*)(lo + i8) = *(uint4*)lb;
}

// ---------------------------------------------------------------------------
// 4) mma.sync bf16 GEMM: C[M,N] = (Ah+Al)[M,K] @ (Bh+Bl)[N,K]^T (3-term)
//    128x128x32 CTA tile, 256 threads = 8 warps (2m x 4n), warp 64x32.
//    cp.async 2-stage pipeline. smem rows padded to 40 bf16 (80 B).
//    MODE 0: store  MODE 1: C = acc + aux  MODE 2: QKV routing
// ---------------------------------------------------------------------------
#define LDT 40                 // bf16 per smem row (32 data + 8 pad)
#define TILE_BYTES (128 * LDT * 2)     // 10240
#define OFF_AH 0
#define OFF_AL (1 * TILE_BYTES)
#define OFF_BH (2 * TILE_BYTES)
#define OFF_BL (3 * TILE_BYTES)
#define STG_BYTES (4 * TILE_BYTES)     // 40960
#define MM_SMEM (2 * STG_BYTES)        // 81920 (>= 128*132*4 epilogue)

__device__ __forceinline__ void bmma_load_stage(
    uint32_t sbase, const __nv_bfloat16* Ah, const __nv_bfloat16* Al,
    const __nv_bfloat16* Bh, const __nv_bfloat16* Bl,
    int m0, int n0, int K, int kc, int tid)
{
    int r = tid >> 2, seg = tid & 3;                 // 64 rows x 4 segs
    size_t kof = (size_t)kc * 32 + seg * 8;          // element offset
    uint32_t dst = sbase + r * 80 + seg * 16;
    const __nv_bfloat16* pa = Ah + (size_t)(m0 + r) * K + kof;
    const __nv_bfloat16* pl = Al + (size_t)(m0 + r) * K + kof;
    const __nv_bfloat16* pb = Bh + (size_t)(n0 + r) * K + kof;
    const __nv_bfloat16* pq = Bl + (size_t)(n0 + r) * K + kof;
    size_t half = (size_t)64 * K;
    CPA(dst + OFF_AH, pa);  CPA(dst + OFF_AH + 64 * 80, pa + half);
    CPA(dst + OFF_AL, pl);  CPA(dst + OFF_AL + 64 * 80, pl + half);
    CPA(dst + OFF_BH, pb);  CPA(dst + OFF_BH + 64 * 80, pb + half);
    CPA(dst + OFF_BL, pq);  CPA(dst + OFF_BL + 64 * 80, pq + half);
}

template <int MODE>
__global__ __launch_bounds__(256)
void k_bmma(const __nv_bfloat16* __restrict__ Ah, const __nv_bfloat16* __restrict__ Al,
            const __nv_bfloat16* __restrict__ Bh, const __nv_bfloat16* __restrict__ Bl,
            float* __restrict__ Cbase, const float* __restrict__ aux,
            int K, int N) {
    extern __shared__ char smem[];
    uint32_t sb = smem_u32(smem);
    int tid = threadIdx.x;
    int m0 = blockIdx.y * 128, n0 = blockIdx.x * 128;
    int warp = tid >> 5, lane = tid & 31;
    int wm = warp >> 2, wn = warp & 3;               // warp tile: 64m x 32n

    float acc[4][4][4];
    #pragma unroll
    for (int i = 0; i < 4; i++)
        #pragma unroll
        for (int j = 0; j < 4; j++)
            #pragma unroll
            for (int v = 0; v < 4; v++) acc[i][j][v] = 0.f;

    // per-thread ldmatrix offsets (within a tile, in bytes)
    uint32_t a_off = (lane & 15) * 80 + (lane >> 4) * 16;             // A: row, kchunk
    uint32_t b_off = ((lane >> 4) * 8 + (lane & 7)) * 80 + ((lane >> 3) & 1) * 16;

    const int KC = K / 32;

    bmma_load_stage(sb, Ah, Al, Bh, Bl, m0, n0, K, 0, tid);
    CPA_COMMIT();

    for (int kc = 0; kc < KC; kc++) {
        int s = kc & 1;
        if (kc + 1 < KC) {
            bmma_load_stage(sb + (s ^ 1) * STG_BYTES, Ah, Al, Bh, Bl, m0, n0, K, kc + 1, tid);
            CPA_COMMIT();
            CPA_WAIT(1);
        } else {
            CPA_WAIT(0);
        }
        __syncthreads();

        uint32_t stg = sb + s * STG_BYTES;
        uint32_t aBase = stg + wm * (64 * 80) + a_off;       // A tiles: +im*16*80
        uint32_t bBase = stg + wn * (32 * 80) + b_off;       // B groups: +g*16*80

        #pragma unroll
        for (int ks = 0; ks < 2; ks++) {
            uint32_t ko = ks * 32;                           // 16 bf16 = 32 bytes
            uint32_t ah[4][4], al[4][4], bh[4][2], bl[4][2];
            // A_hi fragments (4 m16k16 tiles)
            #pragma unroll
            for (int im = 0; im < 4; im++)
                LDSM4(ah[im][0], ah[im][1], ah[im][2], ah[im][3],
                      aBase + OFF_AH + im * (16 * 80) + ko);
            // B_hi fragments (4 n8k16 tiles via 2 x ldmatrix.x4)
            #pragma unroll
            for (int g = 0; g < 2; g++) {
                uint32_t r0, r1, r2, r3;
                LDSM4(r0, r1, r2, r3, bBase + OFF_BH + g * (16 * 80) + ko);
                bh[g * 2 + 0][0] = r0; bh[g * 2 + 0][1] = r1;
                bh[g * 2 + 1][0] = r2; bh[g * 2 + 1][1] = r3;
            }
            #pragma unroll
            for (int im = 0; im < 4; im++)
                #pragma unroll
                for (int in = 0; in < 4; in++)
                    MMA16816(acc[im][in], ah[im][0], ah[im][1], ah[im][2], ah[im][3],
                             bh[in][0], bh[in][1]);
            // B_lo
            #pragma unroll
            for (int g = 0; g < 2; g++) {
                uint32_t r0, r1, r2, r3;
                LDSM4(r0, r1, r2, r3, bBase + OFF_BL + g * (16 * 80) + ko);
                bl[g * 2 + 0][0] = r0; bl[g * 2 + 0][1] = r1;
                bl[g * 2 + 1][0] = r2; bl[g * 2 + 1][1] = r3;
            }
            #pragma unroll
            for (int im = 0; im < 4; im++)
                #pragma unroll
                for (int in = 0; in < 4; in++)
                    MMA16816(acc[im][in], ah[im][0], ah[im][1], ah[im][2], ah[im][3],
                             bl[in][0], bl[in][1]);
            // A_lo x B_hi
            #pragma unroll
            for (int im = 0; im < 4; im++)
                LDSM4(al[im][0], al[im][1], al[im][2], al[im][3],
                      aBase + OFF_AL + im * (16 * 80) + ko);
            #pragma unroll
            for (int im = 0; im < 4; im++)
                #pragma unroll
                for (int in = 0; in < 4; in++)
                    MMA16816(acc[im][in], al[im][0], al[im][1], al[im][2], al[im][3],
                             bh[in][0], bh[in][1]);
        }
        __syncthreads();
    }

    // ---- epilogue: regs -> smem (pitch 132) -> coalesced global ----
    float* stile = (float*)smem;
    int qrow = lane >> 2, qcol = (lane & 3) * 2;
    #pragma unroll
    for (int im = 0; im < 4; im++) {
        int r0 = wm * 64 + im * 16 + qrow;
        #pragma unroll
        for (int in = 0; in < 4; in++) {
            int c = wn * 32 + in * 8 + qcol;
            stile[(size_t)r0 * 132 + c]           = acc[im][in][0];
            stile[(size_t)r0 * 132 + c + 1]       = acc[im][in][1];
            stile[(size_t)(r0 + 8) * 132 + c]     = acc[im][in][2];
            stile[(size_t)(r0 + 8) * 132 + c + 1] = acc[im][in][3];
        }
    }
    __syncthreads();

    float* Cp; int ldc; int ncol;
    if (MODE == 2) {
        if (n0 < NH * HD)             { Cp = g_q; ldc = NH * HD;  ncol = n0; }
        else if (n0 < (NH + NKV) * HD){ Cp = g_k; ldc = NKV * HD; ncol = n0 - NH * HD; }
        else                          { Cp = g_v; ldc = NKV * HD; ncol = n0 - (NH + NKV) * HD; }
    } else { Cp = Cbase; ldc = N; ncol = n0; }

    #pragma unroll
    for (int st = 0; st < 16; st++) {
        int idx = st * 256 + tid;
        int m = idx >> 5;
        int c4 = (idx & 31) * 4;
        const float* srow = &stile[(size_t)m * 132 + c4];
        float4 v;
        v.x = srow[0]; v.y = srow[1]; v.z = srow[2]; v.w = srow[3];
        size_t go = (size_t)(m0 + m) * ldc + ncol + c4;
        if (MODE == 1) {
            float4 a4 = *(const float4*)(aux + go);
            v.x += a4.x; v.y += a4.y; v.z += a4.z; v.w += a4.w;
        }
        *(float4*)(Cp + go) = v;
    }
}

// ---------------------------------------------------------------------------
// 5) per-(t,head) RMSNorm + RoPE (in-place on g_q / g_k)
// ---------------------------------------------------------------------------
__global__ void k_qknorm_rope(const float* __restrict__ cosb,
                              const float* __restrict__ sinb,
                              const float* __restrict__ qw,
                              const float* __restrict__ kw) {
    int t = blockIdx.x;
    int head = blockIdx.y;
    float* buf; const float* w; int off;
    if (head < NH) { buf = g_q; off = (t * NH + head) * HD; w = qw; }
    else           { buf = g_k; off = (t * NKV + (head - NH)) * HD; w = kw; }
    int d = threadIdx.x;
    float v = buf[off + d];
    float ss = v * v;
    #pragma unroll
    for (int o = 16; o; o >>= 1) ss += __shfl_xor_sync(~0u, ss, o);
    __shared__ float ws[4];
    if ((d & 31) == 0) ws[d >> 5] = ss;
    __syncthreads();
    float tot = ws[0] + ws[1] + ws[2] + ws[3];
    float r = rsqrtf(tot * (1.0f / HD) + EPSF);
    __shared__ float sh[HD];
    sh[d] = v * r * w[d];
    __syncthreads();
    float rot = (d < 64) ? -sh[d + 64] : sh[d - 64];
    buf[off + d] = sh[d] * cosb[t * HD + d] + rot * sinb[t * HD + d];
}

// ---------------------------------------------------------------------------
// 6) fp32 flash attention, causal, 64x64 tiles, D=128 -> bf16 hi/lo out
//    softmax stats: 4 threads per row (16 cols each), shfl reduction
// ---------------------------------------------------------------------------
#define ATT_SMEM_FLOATS (64*128 + 128*64 + 64*128 + 64*65 + 3*64)
__global__ __launch_bounds__(256)
void k_attn() {
    extern __shared__ float asm_[];
    float* Qs   = asm_;
    float* Kst  = Qs  + 64 * 128;
    float* Vs   = Kst + 128 * 64;
    float* Ps   = Vs  + 64 * 128;
    float* mrow = Ps  + 64 * 65;
    float* lrow = mrow + 64;
    float* arow = lrow + 64;

    int qt = (int)gridDim.x - 1 - (int)blockIdx.x;
    int h  = blockIdx.y;
    int kvh = h >> 1;
    int tid = threadIdx.x;
    int ty = tid >> 4, tx = tid & 15;

    for (int f = tid; f < 64 * 32; f += 256) {
        int r = f >> 5, d4 = (f & 31) * 4;
        *(float4*)&Qs[r * 128 + d4] =
            *(const float4*)&g_q[(size_t)(qt * 64 + r) * (NH * HD) + h * HD + d4];
    }
    if (tid < 64) { mrow[tid] = -1e30f; lrow[tid] = 0.f; }

    float O[4][8];
    #pragma unroll
    for (int i = 0; i < 4; i++)
        #pragma unroll
        for (int j = 0; j < 8; j++) O[i][j] = 0.f;

    for (int kt = 0; kt <= qt; kt++) {
        for (int f = tid; f < 64 * 32; f += 256) {
            int s = f & 63, d4 = (f >> 6) * 4;
            float4 kv4 = *(const float4*)&g_k[(size_t)(kt * 64 + s) * (NKV * HD) + kvh * HD + d4];
            Kst[(d4 + 0) * 64 + s] = kv4.x;
            Kst[(d4 + 1) * 64 + s] = kv4.y;
            Kst[(d4 + 2) * 64 + s] = kv4.z;
            Kst[(d4 + 3) * 64 + s] = kv4.w;
        }
        for (int f = tid; f < 64 * 32; f += 256) {
            int s = f >> 5, d4 = (f & 31) * 4;
            *(float4*)&Vs[s * 128 + d4] =
                *(const float4*)&g_v[(size_t)(kt * 64 + s) * (NKV * HD) + kvh * HD + d4];
        }
        __syncthreads();

        float sacc[4][4];
        #pragma unroll
        for (int i = 0; i < 4; i++)
            #pragma unroll
            for (int j = 0; j < 4; j++) sacc[i][j] = 0.f;

        #pragma unroll 8
        for (int k4 = 0; k4 < 32; k4++) {
            float a[4][4], b[4][4];
            #pragma unroll
            for (int i = 0; i < 4; i++)
                *(float4*)a[i] = *(const float4*)&Qs[(ty * 4 + i) * 128 + k4 * 4];
            #pragma unroll
            for (int kk = 0; kk < 4; kk++)
                *(float4*)b[kk] = *(const float4*)&Kst[(k4 * 4 + kk) * 64 + tx * 4];
            #pragma unroll
            for (int kk = 0; kk < 4; kk++)
                #pragma unroll
                for (int i = 0; i < 4; i++)
                    #pragma unroll
                    for (int j = 0; j < 4; j++)
                        sacc[i][j] += a[i][kk] * b[kk][j];
        }

        bool diag = (kt == qt);
        #pragma unroll
        for (int i = 0; i < 4; i++)
            #pragma unroll
            for (int j = 0; j < 4; j++) {
                float sv = sacc[i][j] * SCALEF;
                if (diag && (tx * 4 + j) > (ty * 4 + i)) sv = -1e30f;
                Ps[(ty * 4 + i) * 65 + tx * 4 + j] = sv;
            }
        __syncthreads();

        // row stats: 4 threads per row, 16 cols each, shfl reduce over the quad
        {
            int r = tid >> 2, qd = tid & 3;
            float* prow = &Ps[r * 65 + qd * 16];
            float mx = prow[0];
            #pragma unroll
            for (int s2 = 1; s2 < 16; s2++) mx = fmaxf(mx, prow[s2]);
            mx = fmaxf(mx, __shfl_xor_sync(~0u, mx, 1));
            mx = fmaxf(mx, __shfl_xor_sync(~0u, mx, 2));
            float mold = mrow[r];
            mx = fmaxf(mx, mold);
            float alpha = expf(mold - mx);
            float lp = 0.f;
            #pragma unroll
            for (int s2 = 0; s2 < 16; s2++) {
                float p = expf(prow[s2] - mx);
                prow[s2] = p;
                lp += p;
            }
            lp += __shfl_xor_sync(~0u, lp, 1);
            lp += __shfl_xor_sync(~0u, lp, 2);
            if (qd == 0) {
                mrow[r] = mx;
                lrow[r] = lrow[r] * alpha + lp;
                arow[r] = alpha;
            }
        }
        __syncthreads();

        #pragma unroll
        for (int i = 0; i < 4; i++) {
            float al = arow[ty * 4 + i];
            #pragma unroll
            for (int j = 0; j < 8; j++) O[i][j] *= al;
        }
        #pragma unroll 4
        for (int s2 = 0; s2 < 64; s2++) {
            float p[4];
            #pragma unroll
            for (int i = 0; i < 4; i++) p[i] = Ps[(ty * 4 + i) * 65 + s2];
            float4 v0 = *(const float4*)&Vs[s2 * 128 + tx * 8];
            float4 v1 = *(const float4*)&Vs[s2 * 128 + tx * 8 + 4];
            #pragma unroll
            for (int i = 0; i < 4; i++) {
                O[i][0] += p[i] * v0.x; O[i][1] += p[i] * v0.y;
                O[i][2] += p[i] * v0.z; O[i][3] += p[i] * v0.w;
                O[i][4] += p[i] * v1.x; O[i][5] += p[i] * v1.y;
                O[i][6] += p[i] * v1.z; O[i][7] += p[i] * v1.w;
            }
        }
        __syncthreads();
    }

    #pragma unroll
    for (int i = 0; i < 4; i++) {
        int r = ty * 4 + i;
        int t = qt * 64 + r;
        float inv = 1.0f / lrow[r];
        #pragma unroll
        for (int j = 0; j < 8; j++) {
            float v = O[i][j] * inv;
            size_t o = (size_t)t * (NH * HD) + h * HD + tx * 8 + j;
            __nv_bfloat16 hv = __float2bfloat16(v);
            g_ao_hi[o] = hv;
            g_ao_lo[o] = __float2bfloat16(v - __bfloat162float(hv));
        }
    }
}

// ---------------------------------------------------------------------------
// 7) post-attention RMSNorm -> h2 bf16 hi/lo
// ---------------------------------------------------------------------------
__global__ void k_rms_post(const float* __restrict__ w) {
    int t = blockIdx.x;
    int tid = threadIdx.x;                   // 256
    const float* row = g_hidden + (size_t)t * HIDD;
    float ss = 0.f;
    for (int c = tid; c < HIDD; c += 256) { float v = row[c]; ss += v * v; }
    #pragma unroll
    for (int o = 16; o; o >>= 1) ss += __shfl_xor_sync(~0u, ss, o);
    __shared__ float wsum[8];
    if ((tid & 31) == 0) wsum[tid >> 5] = ss;
    __syncthreads();
    if (tid < 32) {
        float s = (tid < 8) ? wsum[tid] : 0.f;
        #pragma unroll
        for (int o = 4; o; o >>= 1) s += __shfl_xor_sync(~0u, s, o);
        if (tid == 0) wsum[0] = rsqrtf(s * (1.0f / HIDD) + EPSF);
    }
    __syncthreads();
    float r = wsum[0];
    for (int c = tid; c < HIDD; c += 256) {
        float nv = row[c] * r * w[c];
        __nv_bfloat16 hv = __float2bfloat16(nv);
        g_h2_hi[(size_t)t * HIDD + c] = hv;
        g_h2_lo[(size_t)t * HIDD + c] = __float2bfloat16(nv - __bfloat162float(hv));
    }
}

// ---------------------------------------------------------------------------
// 8) SwiGLU -> act bf16 hi/lo (4 elems/thread, vector I/O)
// ---------------------------------------------------------------------------
__global__ void k_swiglu() {
    int t = blockIdx.y;
    int i = (blockIdx.x * 256 + threadIdx.x) * 4;
    float4 g4 = *(const float4*)&g_gu[(size_t)t * (2 * II) + i];
    float4 u4 = *(const float4*)&g_gu[(size_t)t * (2 * II) + II + i];
    float gg[4] = {g4.x, g4.y, g4.z, g4.w};
    float uu[4] = {u4.x, u4.y, u4.z, u4.w};
    __nv_bfloat16 hb[4], lb[4];
    #pragma unroll
    for (int j = 0; j < 4; j++) {
        float a = (gg[j] / (1.0f + expf(-gg[j]))) * uu[j];
        hb[j] = __float2bfloat16(a);
        lb[j] = __float2bfloat16(a - __bfloat162float(hb[j]));
    }
    *(uint2*)&g_act_hi[(size_t)t * II + i] = *(uint2*)hb;
    *(uint2*)&g_act_lo[(size_t)t * II + i] = *(uint2*)lb;
}

// ---------------------------------------------------------------------------
// 9) final transpose: out[c*T + t] = g_final[t*HID + c]
// ---------------------------------------------------------------------------
__global__ void k_transpose_out(float* __restrict__ out) {
    __shared__ float tile[32][33];
    int t0 = blockIdx.x * 32, c0 = blockIdx.y * 32;
    int tx = threadIdx.x, ty = threadIdx.y;     // 32 x 8
    for (int i = ty; i < 32; i += 8)
        tile[i][tx] = g_final[(size_t)(t0 + i) * HIDD + c0 + tx];
    __syncthreads();
    for (int i = ty; i < 32; i += 8)
        out[(size_t)(c0 + i) * TT + t0 + tx] = tile[tx][i];
}

// ---------------------------------------------------------------------------
// launch
// ---------------------------------------------------------------------------
extern "C" void kernel_launch(void* const* d_in, const int* in_sizes, int n_in,
                              void* d_out, int out_size) {
    const float* hc   = (const float*)d_in[0];
    const float* cosb = (const float*)d_in[1];
    const float* sinb = (const float*)d_in[2];
    // d_in[3] causal_mask, d_in[4] kv_cache, d_in[15] current_pos: unused
    const float* wq  = (const float*)d_in[5];
    const float* wk  = (const float*)d_in[6];
    const float* wv  = (const float*)d_in[7];
    const float* wo  = (const float*)d_in[8];
    const float* wgu = (const float*)d_in[9];
    const float* wd  = (const float*)d_in[10];
    const float* ilw = (const float*)d_in[11];
    const float* plw = (const float*)d_in[12];
    const float* qnw = (const float*)d_in[13];
    const float* knw = (const float*)d_in[14];
    float* out = (float*)d_out;

    float *p_x, *p_hid, *p_gu, *p_fin;
    cudaGetSymbolAddress((void**)&p_x,   g_x);
    cudaGetSymbolAddress((void**)&p_hid, g_hidden);
    cudaGetSymbolAddress((void**)&p_gu,  g_gu);
    cudaGetSymbolAddress((void**)&p_fin, g_final);

    __nv_bfloat16 *b_h_hi, *b_h_lo, *b_h2_hi, *b_h2_lo, *b_ao_hi, *b_ao_lo,
                  *b_act_hi, *b_act_lo, *b_wqkv_hi, *b_wqkv_lo, *b_wo_hi, *b_wo_lo,
                  *b_wgu_hi, *b_wgu_lo, *b_wd_hi, *b_wd_lo;
    cudaGetSymbolAddress((void**)&b_h_hi,   g_h_hi);
    cudaGetSymbolAddress((void**)&b_h_lo,   g_h_lo);
    cudaGetSymbolAddress((void**)&b_h2_hi,  g_h2_hi);
    cudaGetSymbolAddress((void**)&b_h2_lo,  g_h2_lo);
    cudaGetSymbolAddress((void**)&b_ao_hi,  g_ao_hi);
    cudaGetSymbolAddress((void**)&b_ao_lo,  g_ao_lo);
    cudaGetSymbolAddress((void**)&b_act_hi, g_act_hi);
    cudaGetSymbolAddress((void**)&b_act_lo, g_act_lo);
    cudaGetSymbolAddress((void**)&b_wqkv_hi, g_wqkv_hi);
    cudaGetSymbolAddress((void**)&b_wqkv_lo, g_wqkv_lo);
    cudaGetSymbolAddress((void**)&b_wo_hi,  g_wo_hi);
    cudaGetSymbolAddress((void**)&b_wo_lo,  g_wo_lo);
    cudaGetSymbolAddress((void**)&b_wgu_hi, g_wgu_hi);
    cudaGetSymbolAddress((void**)&b_wgu_lo, g_wgu_lo);
    cudaGetSymbolAddress((void**)&b_wd_hi,  g_wd_hi);
    cudaGetSymbolAddress((void**)&b_wd_lo,  g_wd_lo);

    const int ATT_SMEM = ATT_SMEM_FLOATS * 4;
    cudaFuncSetAttribute(k_attn, cudaFuncAttributeMaxDynamicSharedMemorySize, ATT_SMEM);
    cudaFuncSetAttribute(k_bmma<0>, cudaFuncAttributeMaxDynamicSharedMemorySize, MM_SMEM);
    cudaFuncSetAttribute(k_bmma<1>, cudaFuncAttributeMaxDynamicSharedMemorySize, MM_SMEM);
    cudaFuncSetAttribute(k_bmma<2>, cudaFuncAttributeMaxDynamicSharedMemorySize, MM_SMEM);

    // weight conversions (independent of activations)
    k_wconv<<<(NH * HD * HIDD) / 2048, 256>>>(wq, b_wqkv_hi, b_wqkv_lo, NH * HD * HIDD);
    k_wconv<<<(NKV * HD * HIDD) / 2048, 256>>>(wk, b_wqkv_hi + (size_t)NH * HD * HIDD,
                                               b_wqkv_lo + (size_t)NH * HD * HIDD, NKV * HD * HIDD);
    k_wconv<<<(NKV * HD * HIDD) / 2048, 256>>>(wv, b_wqkv_hi + (size_t)(NH + NKV) * HD * HIDD,
                                               b_wqkv_lo + (size_t)(NH + NKV) * HD * HIDD, NKV * HD * HIDD);
    k_wconv<<<(HIDD * NH * HD) / 2048, 256>>>(wo, b_wo_hi, b_wo_lo, HIDD * NH * HD);
    k_wconv<<<(2 * II * HIDD) / 2048, 256>>>(wgu, b_wgu_hi, b_wgu_lo, 2 * II * HIDD);
    k_wconv<<<(HIDD * II) / 2048, 256>>>(wd, b_wd_hi, b_wd_lo, HIDD * II);

    // 1-2) input RMSNorm + transpose (also emits raw x)
    k_rms_in_pass1<<<TT / 32, dim3(32, 8)>>>(hc);
    k_norm_transpose<<<dim3(TT / 32, HIDD / 32), dim3(32, 8)>>>(hc, ilw);

    // 3) fused QKV projection (tensor cores, routed epilogue)
    k_bmma<2><<<dim3((NH + 2 * NKV) * HD / 128, TT / 128), 256, MM_SMEM>>>(
        b_h_hi, b_h_lo, b_wqkv_hi, b_wqkv_lo, nullptr, nullptr, HIDD, (NH + 2 * NKV) * HD);

    // 4) q/k RMSNorm + RoPE
    k_qknorm_rope<<<dim3(TT, NH + NKV), HD>>>(cosb, sinb, qnw, knw);

    // 5) causal flash attention (fp32, bf16 hi/lo out)
    k_attn<<<dim3(TT / 64, NH), 256, ATT_SMEM>>>();

    // 6) Wo projection + residual(x)
    k_bmma<1><<<dim3(HIDD / 128, TT / 128), 256, MM_SMEM>>>(
        b_ao_hi, b_ao_lo, b_wo_hi, b_wo_lo, p_hid, p_x, NH * HD, HIDD);

    // 7) post-LN
    k_rms_post<<<TT, 256>>>(plw);

    // 8) gate_up GEMM
    k_bmma<0><<<dim3((2 * II) / 128, TT / 128), 256, MM_SMEM>>>(
        b_h2_hi, b_h2_lo, b_wgu_hi, b_wgu_lo, p_gu, nullptr, HIDD, 2 * II);

    // 9) SwiGLU
    k_swiglu<<<dim3(II / 1024, TT), 256>>>();

    // 10) down GEMM + residual
    k_bmma<1><<<dim3(HIDD / 128, TT / 128), 256, MM_SMEM>>>(
        b_act_hi, b_act_lo, b_wd_hi, b_wd_lo, p_fin, p_hid, II, HIDD);

    // 11) output transpose
    k_transpose_out<<<dim3(TT / 32, HIDD / 32), dim3(32, 8)>>>(out);
}